// round 9
// baseline (speedup 1.0000x reference)
#include <cuda_runtime.h>
#include <cuda_bf16.h>
#include <cstdint>

#define N_NODES 50000
#define N_EDGES 800000
#define N_GRAPHS 64
#define FEAT 128
#define EMB 256
#define HID 512
#define VOCAB 512
#define NBLK_SCAN ((N_NODES + 255) / 256)   // 196

// ---------------- scratch (device globals; no allocation allowed) ----------
__device__ float g_aggin1[(size_t)N_NODES * FEAT];
__device__ float g_aggin2[(size_t)N_NODES * EMB];
__device__ float g_h1[(size_t)N_NODES * EMB];
__device__ int   g_deg[N_NODES];
__device__ int   g_rowstart[N_NODES];
__device__ int   g_cursor[N_NODES];
__device__ int   g_srcs[N_EDGES];
__device__ int   g_bsum[NBLK_SCAN];
__device__ int   g_boff[NBLK_SCAN];
__device__ float g_pooled[N_GRAPHS * HID];
__device__ float g_gcnt[N_GRAPHS];

// bf16 hi/lo weight copies: W_root1 @0 (32768), W_rel1 @32768,
// W_root2 @65536 (131072), W_rel2 @196608 (131072). total 327680.
#define W_TOTAL 327680
__device__ __nv_bfloat16 g_whi[W_TOTAL];
__device__ __nv_bfloat16 g_wlo[W_TOTAL];

// ---------------- small helpers ---------------------------------------------
__device__ __forceinline__ uint32_t smem_u32(const void* p) {
    return (uint32_t)__cvta_generic_to_shared(p);
}
__device__ __forceinline__ void ldsm_x4(uint32_t& r0, uint32_t& r1,
                                        uint32_t& r2, uint32_t& r3, uint32_t a) {
    asm volatile("ldmatrix.sync.aligned.m8n8.x4.shared.b16 {%0,%1,%2,%3},[%4];"
                 : "=r"(r0), "=r"(r1), "=r"(r2), "=r"(r3) : "r"(a));
}
__device__ __forceinline__ void ldsm_x4t(uint32_t& r0, uint32_t& r1,
                                         uint32_t& r2, uint32_t& r3, uint32_t a) {
    asm volatile("ldmatrix.sync.aligned.m8n8.x4.trans.shared.b16 {%0,%1,%2,%3},[%4];"
                 : "=r"(r0), "=r"(r1), "=r"(r2), "=r"(r3) : "r"(a));
}
__device__ __forceinline__ void mma_bf16(float* c, const uint32_t* a, const uint32_t* b) {
    asm volatile(
        "mma.sync.aligned.m16n8k16.row.col.f32.bf16.bf16.f32 "
        "{%0,%1,%2,%3},{%4,%5,%6,%7},{%8,%9},{%0,%1,%2,%3};"
        : "+f"(c[0]), "+f"(c[1]), "+f"(c[2]), "+f"(c[3])
        : "r"(a[0]), "r"(a[1]), "r"(a[2]), "r"(a[3]), "r"(b[0]), "r"(b[1]));
}
__device__ __forceinline__ uint32_t pack_bf2(__nv_bfloat16 x, __nv_bfloat16 y) {
    __nv_bfloat162 v = __halves2bfloat162(x, y);
    return *reinterpret_cast<uint32_t*>(&v);
}

// ---------------- weight split + zero scratch (merged) ----------------------
__global__ void k_wconv_zero(const float* __restrict__ w0, const float* __restrict__ w1,
                             const float* __restrict__ w2, const float* __restrict__ w3) {
    int i0 = blockIdx.x * blockDim.x + threadIdx.x;
    int stride = gridDim.x * blockDim.x;
    for (int i = i0; i < W_TOTAL; i += stride) {
        const float* src; int off;
        if (i < 32768)       { src = w0; off = i; }
        else if (i < 65536)  { src = w1; off = i - 32768; }
        else if (i < 196608) { src = w2; off = i - 65536; }
        else                 { src = w3; off = i - 196608; }
        float v = src[off];
        __nv_bfloat16 h = __float2bfloat16(v);
        g_whi[i] = h;
        g_wlo[i] = __float2bfloat16(v - __bfloat162float(h));
    }
    for (int j = i0; j < N_NODES; j += stride) g_deg[j] = 0;
    for (int j = i0; j < N_GRAPHS * HID; j += stride) g_pooled[j] = 0.f;
    for (int j = i0; j < N_GRAPHS; j += stride) g_gcnt[j] = 0.f;
}

// ---------------- in-degree histogram + per-graph counts (merged) -----------
__global__ void k_hist(const int* __restrict__ ei, const int* __restrict__ batch) {
    int i = blockIdx.x * blockDim.x + threadIdx.x;
    int stride = gridDim.x * blockDim.x;
    for (int e = i; e < N_EDGES; e += stride)
        atomicAdd(&g_deg[ei[N_EDGES + e]], 1);
    for (int v = i; v < N_NODES; v += stride)
        atomicAdd(&g_gcnt[batch[v]], 1.f);
}

// ---------------- 3-phase multi-block exclusive scan of g_deg ----------------
__global__ __launch_bounds__(256)
void k_scan1() {                       // per-block sums
    __shared__ int red[8];
    int b = blockIdx.x, t = threadIdx.x;
    int idx = b * 256 + t;
    int v = (idx < N_NODES) ? g_deg[idx] : 0;
    #pragma unroll
    for (int o = 16; o > 0; o >>= 1) v += __shfl_down_sync(0xffffffffu, v, o);
    if ((t & 31) == 0) red[t >> 5] = v;
    __syncthreads();
    if (t < 8) {
        int s = red[t];
        #pragma unroll
        for (int o = 4; o > 0; o >>= 1) s += __shfl_down_sync(0xffu, s, o);
        if (t == 0) g_bsum[b] = s;
    }
}

__global__ __launch_bounds__(256)
void k_scan2() {                       // scan of 196 block sums (1 block)
    __shared__ int s[256];
    int t = threadIdx.x;
    int v = (t < NBLK_SCAN) ? g_bsum[t] : 0;
    s[t] = v;
    __syncthreads();
    for (int off = 1; off < 256; off <<= 1) {
        int u = (t >= off) ? s[t - off] : 0;
        __syncthreads();
        s[t] += u;
        __syncthreads();
    }
    if (t < NBLK_SCAN) g_boff[t] = (t == 0) ? 0 : s[t - 1];
}

__global__ __launch_bounds__(256)
void k_scan3() {                       // local scan + block offset
    __shared__ int s[256];
    int b = blockIdx.x, t = threadIdx.x;
    int idx = b * 256 + t;
    int v = (idx < N_NODES) ? g_deg[idx] : 0;
    s[t] = v;
    __syncthreads();
    for (int off = 1; off < 256; off <<= 1) {
        int u = (t >= off) ? s[t - off] : 0;
        __syncthreads();
        s[t] += u;
        __syncthreads();
    }
    if (idx < N_NODES) {
        int excl = ((t == 0) ? 0 : s[t - 1]) + g_boff[b];
        g_rowstart[idx] = excl;
        g_cursor[idx] = excl;
    }
}

// ---------------- fill sorted src list by dst bin ----------------------------
__global__ void k_fill(const int* __restrict__ ei) {
    int i = blockIdx.x * blockDim.x + threadIdx.x;
    int stride = gridDim.x * blockDim.x;
    for (int e = i; e < N_EDGES; e += stride) {
        int src = ei[e];
        int dst = ei[N_EDGES + e];
        int pos = atomicAdd(&g_cursor[dst], 1);
        g_srcs[pos] = src;
    }
}

// ---------------- gather: warp per node, agg[v] = mean of feat[src] ---------
// F4 = number of float4 per lane (F/128). cols handled: lane*4 + c*128
template<int F4>
__global__ __launch_bounds__(256)
void k_gather_w(const float* __restrict__ feat, float* __restrict__ agg) {
    const int F = F4 * 128;
    int w = (blockIdx.x * blockDim.x + threadIdx.x) >> 5;
    if (w >= N_NODES) return;
    int lane = threadIdx.x & 31;
    int start = g_rowstart[w];
    int d = g_deg[w];

    float4 acc[4][F4];
    #pragma unroll
    for (int u = 0; u < 4; u++)
        #pragma unroll
        for (int c = 0; c < F4; c++)
            acc[u][c] = make_float4(0.f, 0.f, 0.f, 0.f);

    int i = 0;
    for (; i + 4 <= d; i += 4) {
        #pragma unroll
        for (int u = 0; u < 4; u++) {
            int src = g_srcs[start + i + u];
            const float* row = feat + (long long)src * F + lane * 4;
            #pragma unroll
            for (int c = 0; c < F4; c++) {
                float4 v = *reinterpret_cast<const float4*>(row + c * 128);
                acc[u][c].x += v.x; acc[u][c].y += v.y;
                acc[u][c].z += v.z; acc[u][c].w += v.w;
            }
        }
    }
    for (; i < d; i++) {
        int src = g_srcs[start + i];
        const float* row = feat + (long long)src * F + lane * 4;
        #pragma unroll
        for (int c = 0; c < F4; c++) {
            float4 v = *reinterpret_cast<const float4*>(row + c * 128);
            acc[0][c].x += v.x; acc[0][c].y += v.y;
            acc[0][c].z += v.z; acc[0][c].w += v.w;
        }
    }
    float inv = 1.f / fmaxf((float)d, 1.f);
    float* dstrow = agg + (long long)w * F + lane * 4;
    #pragma unroll
    for (int c = 0; c < F4; c++) {
        float4 r;
        r.x = (acc[0][c].x + acc[1][c].x + acc[2][c].x + acc[3][c].x) * inv;
        r.y = (acc[0][c].y + acc[1][c].y + acc[2][c].y + acc[3][c].y) * inv;
        r.z = (acc[0][c].z + acc[1][c].z + acc[2][c].z + acc[3][c].z) * inv;
        r.w = (acc[0][c].w + acc[1][c].w + acc[2][c].w + acc[3][c].w) * inv;
        *reinterpret_cast<float4*>(dstrow + c * 128) = r;
    }
}

// ---------------- tensor-core dual GEMM (bf16x3 fp32 emulation) -------------
// C[M,N] = relu(A1@B1 + A2@B2 + bias)
// POOL=0: store C.  POOL=1: segment-reduce by batch[] into g_pooled.
#define GBM 128
#define GBN 128
#define GBK 32
#define SA 40
#define SB 136

template<int POOL>
__global__ __launch_bounds__(256, 2)
void k_gemm_tc(const float* __restrict__ A1,
               const __nv_bfloat16* __restrict__ B1h, const __nv_bfloat16* __restrict__ B1l,
               int K1,
               const float* __restrict__ A2,
               const __nv_bfloat16* __restrict__ B2h, const __nv_bfloat16* __restrict__ B2l,
               int K2,
               const float* __restrict__ bias,
               float* __restrict__ C,
               const int* __restrict__ batch,
               int M, int N) {
    __shared__ __align__(16) __nv_bfloat16 Ash[GBM * SA];
    __shared__ __align__(16) __nv_bfloat16 Asl[GBM * SA];
    __shared__ __align__(16) __nv_bfloat16 Bsh[GBK * SB];
    __shared__ __align__(16) __nv_bfloat16 Bsl[GBK * SB];

    int tid = threadIdx.x, lane = tid & 31, warp = tid >> 5;
    int wm = warp & 3, wn = warp >> 2;
    int bm = blockIdx.x * GBM, bn = blockIdx.y * GBN;

    float acc[2][8][4];
    #pragma unroll
    for (int mi = 0; mi < 2; mi++)
        #pragma unroll
        for (int ni = 0; ni < 8; ni++)
            #pragma unroll
            for (int r = 0; r < 4; r++) acc[mi][ni][r] = 0.f;

    int a_row16 = lane & 15;
    int a_koff = (lane >> 4) << 3;
    int b_krow = lane & 15;
    int b_noff = (lane >> 4) << 3;

    for (int pass = 0; pass < 2; pass++) {
        const float* A = pass ? A2 : A1;
        const __nv_bfloat16* Bhg = pass ? B2h : B1h;
        const __nv_bfloat16* Blg = pass ? B2l : B1l;
        int K = pass ? K2 : K1;

        for (int k0 = 0; k0 < K; k0 += GBK) {
            #pragma unroll
            for (int i = 0; i < 4; i++) {
                int f4 = tid + i * 256;
                int row = f4 >> 3;
                int c4 = (f4 & 7) * 4;
                float4 v = make_float4(0.f, 0.f, 0.f, 0.f);
                int gr = bm + row;
                if (gr < M)
                    v = *reinterpret_cast<const float4*>(A + (long long)gr * K + k0 + c4);
                __nv_bfloat16 hx = __float2bfloat16(v.x);
                __nv_bfloat16 hy = __float2bfloat16(v.y);
                __nv_bfloat16 hz = __float2bfloat16(v.z);
                __nv_bfloat16 hw = __float2bfloat16(v.w);
                uint2 hp = make_uint2(pack_bf2(hx, hy), pack_bf2(hz, hw));
                *reinterpret_cast<uint2*>(&Ash[row * SA + c4]) = hp;
                __nv_bfloat16 lx = __float2bfloat16(v.x - __bfloat162float(hx));
                __nv_bfloat16 ly = __float2bfloat16(v.y - __bfloat162float(hy));
                __nv_bfloat16 lz = __float2bfloat16(v.z - __bfloat162float(hz));
                __nv_bfloat16 lw = __float2bfloat16(v.w - __bfloat162float(hw));
                uint2 lp = make_uint2(pack_bf2(lx, ly), pack_bf2(lz, lw));
                *reinterpret_cast<uint2*>(&Asl[row * SA + c4]) = lp;
            }
            #pragma unroll
            for (int i = 0; i < 4; i++) {
                int f = tid + i * 256;
                const __nv_bfloat16* src = (f < 512) ? Bhg : Blg;
                __nv_bfloat16* dst = (f < 512) ? Bsh : Bsl;
                int rem = f & 511;
                int r = rem >> 4;
                int c8 = (rem & 15) * 8;
                uint4 v = *reinterpret_cast<const uint4*>(
                    src + (long long)(k0 + r) * N + bn + c8);
                *reinterpret_cast<uint4*>(dst + r * SB + c8) = v;
            }
            __syncthreads();

            #pragma unroll
            for (int kk = 0; kk < GBK; kk += 16) {
                uint32_t afh[2][4], afl[2][4];
                #pragma unroll
                for (int mi = 0; mi < 2; mi++) {
                    int row = wm * 32 + mi * 16 + a_row16;
                    ldsm_x4(afh[mi][0], afh[mi][1], afh[mi][2], afh[mi][3],
                            smem_u32(&Ash[row * SA + kk + a_koff]));
                    ldsm_x4(afl[mi][0], afl[mi][1], afl[mi][2], afl[mi][3],
                            smem_u32(&Asl[row * SA + kk + a_koff]));
                }
                #pragma unroll
                for (int nj = 0; nj < 4; nj++) {
                    int ncol = wn * 64 + nj * 16 + b_noff;
                    int krow = kk + b_krow;
                    uint32_t bh[4], bl[4];
                    ldsm_x4t(bh[0], bh[1], bh[2], bh[3],
                             smem_u32(&Bsh[krow * SB + ncol]));
                    ldsm_x4t(bl[0], bl[1], bl[2], bl[3],
                             smem_u32(&Bsl[krow * SB + ncol]));
                    #pragma unroll
                    for (int mi = 0; mi < 2; mi++) {
                        mma_bf16(acc[mi][nj * 2],     afh[mi], bh);
                        mma_bf16(acc[mi][nj * 2],     afh[mi], bl);
                        mma_bf16(acc[mi][nj * 2],     afl[mi], bh);
                        mma_bf16(acc[mi][nj * 2 + 1], afh[mi], bh + 2);
                        mma_bf16(acc[mi][nj * 2 + 1], afh[mi], bl + 2);
                        mma_bf16(acc[mi][nj * 2 + 1], afl[mi], bh + 2);
                    }
                }
            }
            __syncthreads();
        }
    }

    int g = lane >> 2, tg = lane & 3;
    int m0 = bm + wm * 32;
    int coln = bn + wn * 64;

    float bb[16];
    #pragma unroll
    for (int ni = 0; ni < 8; ni++) {
        bb[ni * 2]     = bias[coln + ni * 8 + tg * 2];
        bb[ni * 2 + 1] = bias[coln + ni * 8 + tg * 2 + 1];
    }

    if (POOL == 0) {
        #pragma unroll
        for (int mi = 0; mi < 2; mi++) {
            int row_lo = m0 + mi * 16 + g;
            int row_hi = row_lo + 8;
            #pragma unroll
            for (int ni = 0; ni < 8; ni++) {
                int col = coln + ni * 8 + tg * 2;
                if (row_lo < M) {
                    float2 v;
                    v.x = fmaxf(acc[mi][ni][0] + bb[ni * 2], 0.f);
                    v.y = fmaxf(acc[mi][ni][1] + bb[ni * 2 + 1], 0.f);
                    *reinterpret_cast<float2*>(C + (long long)row_lo * N + col) = v;
                }
                if (row_hi < M) {
                    float2 v;
                    v.x = fmaxf(acc[mi][ni][2] + bb[ni * 2], 0.f);
                    v.y = fmaxf(acc[mi][ni][3] + bb[ni * 2 + 1], 0.f);
                    *reinterpret_cast<float2*>(C + (long long)row_hi * N + col) = v;
                }
            }
        }
    } else {
        float sum[16];
        int prev = -1;
        #pragma unroll
        for (int slot = 0; slot < 4; slot++) {
            int mi = slot >> 1, half = slot & 1;
            int row = m0 + mi * 16 + half * 8 + g;
            if (row >= M) break;
            float v[16];
            #pragma unroll
            for (int ni = 0; ni < 8; ni++) {
                v[ni * 2]     = fmaxf(acc[mi][ni][half * 2]     + bb[ni * 2], 0.f);
                v[ni * 2 + 1] = fmaxf(acc[mi][ni][half * 2 + 1] + bb[ni * 2 + 1], 0.f);
            }
            int gid = batch[row];
            if (gid != prev) {
                if (prev >= 0) {
                    #pragma unroll
                    for (int j = 0; j < 16; j++)
                        atomicAdd(&g_pooled[prev * HID + coln + (j >> 1) * 8 + tg * 2 + (j & 1)],
                                  sum[j]);
                }
                prev = gid;
                #pragma unroll
                for (int j = 0; j < 16; j++) sum[j] = v[j];
            } else {
                #pragma unroll
                for (int j = 0; j < 16; j++) sum[j] += v[j];
            }
        }
        if (prev >= 0) {
            #pragma unroll
            for (int j = 0; j < 16; j++)
                atomicAdd(&g_pooled[prev * HID + coln + (j >> 1) * 8 + tg * 2 + (j & 1)],
                          sum[j]);
        }
    }
}

// ---------------- heads -----------------------------------------------------
__global__ __launch_bounds__(512)
void k_head(const float* __restrict__ Wh, const float* __restrict__ bh,
            const float* __restrict__ Wc, const float* __restrict__ bc,
            float* __restrict__ out_hidden, float* __restrict__ out_cell) {
    int g = blockIdx.x;
    int t = threadIdx.x;
    __shared__ float p[HID];
    float inv = 1.f / fmaxf(g_gcnt[g], 1.f);
    p[t] = g_pooled[g * HID + t] * inv;
    __syncthreads();
    float h = 0.f, c = 0.f;
    #pragma unroll 8
    for (int k = 0; k < HID; k++) {
        float pk = p[k];
        h = fmaf(pk, Wh[k * HID + t], h);
        c = fmaf(pk, Wc[k * HID + t], c);
    }
    out_hidden[g * HID + t] = h + bh[t];
    out_cell[g * HID + t]   = c + bc[t];
}

// ---------------- logits = log_softmax(hidden @ Wout + bout) ----------------
__global__ __launch_bounds__(512)
void k_logits(const float* __restrict__ hidden,
              const float* __restrict__ Wout, const float* __restrict__ bout,
              float* __restrict__ logits) {
    int g = blockIdx.x;
    int t = threadIdx.x;
    __shared__ float h[HID];
    __shared__ float red[VOCAB];
    h[t] = hidden[g * HID + t];
    __syncthreads();
    float z = bout[t];
    #pragma unroll 8
    for (int k = 0; k < HID; k++)
        z = fmaf(h[k], Wout[k * VOCAB + t], z);

    red[t] = z;
    __syncthreads();
    for (int s = 256; s > 0; s >>= 1) {
        if (t < s) red[t] = fmaxf(red[t], red[t + s]);
        __syncthreads();
    }
    float mx = red[0];
    __syncthreads();
    red[t] = expf(z - mx);
    __syncthreads();
    for (int s = 256; s > 0; s >>= 1) {
        if (t < s) red[t] += red[t + s];
        __syncthreads();
    }
    float lse = logf(red[0]) + mx;
    logits[g * VOCAB + t] = z - lse;
}

// ---------------- launch ----------------------------------------------------
extern "C" void kernel_launch(void* const* d_in, const int* in_sizes, int n_in,
                              void* d_out, int out_size) {
    const float* x       = (const float*)d_in[1];
    const int*   ei      = (const int*)d_in[2];
    const int*   batch   = (const int*)d_in[3];
    const float* W_root1 = (const float*)d_in[4];
    const float* W_rel1  = (const float*)d_in[5];
    const float* b1      = (const float*)d_in[6];
    const float* W_root2 = (const float*)d_in[7];
    const float* W_rel2  = (const float*)d_in[8];
    const float* b2      = (const float*)d_in[9];
    const float* Wh      = (const float*)d_in[10];
    const float* bh      = (const float*)d_in[11];
    const float* Wc      = (const float*)d_in[12];
    const float* bc      = (const float*)d_in[13];
    const float* Wout    = (const float*)d_in[14];
    const float* bout    = (const float*)d_in[15];
    float* out = (float*)d_out;

    float *p_aggin1, *p_aggin2, *p_h1;
    __nv_bfloat16 *p_whi, *p_wlo;
    cudaGetSymbolAddress((void**)&p_aggin1, g_aggin1);
    cudaGetSymbolAddress((void**)&p_aggin2, g_aggin2);
    cudaGetSymbolAddress((void**)&p_h1, g_h1);
    cudaGetSymbolAddress((void**)&p_whi, g_whi);
    cudaGetSymbolAddress((void**)&p_wlo, g_wlo);

    float* out_logits = out;
    float* out_hidden = out + N_GRAPHS * HID;
    float* out_cell   = out + 2 * N_GRAPHS * HID;

    // 1. weight split + zero scratch, then CSR build (multi-block scan)
    k_wconv_zero<<<320, 256>>>(W_root1, W_rel1, W_root2, W_rel2);
    k_hist<<<1024, 256>>>(ei, batch);
    k_scan1<<<NBLK_SCAN, 256>>>();
    k_scan2<<<1, 256>>>();
    k_scan3<<<NBLK_SCAN, 256>>>();
    k_fill<<<1024, 256>>>(ei);

    // 2. gather mean of raw x into aggin1 (warp per node)
    k_gather_w<1><<<(N_NODES + 7) / 8, 256>>>(x, p_aggin1);

    // 3. h1 = relu(x@W_root1 + aggin1@W_rel1 + b1)   [tensor core]
    {
        dim3 grid((N_NODES + GBM - 1) / GBM, EMB / GBN);
        k_gemm_tc<0><<<grid, 256>>>(x, p_whi, p_wlo, FEAT,
                                    p_aggin1, p_whi + 32768, p_wlo + 32768, FEAT,
                                    b1, p_h1, nullptr, N_NODES, EMB);
    }

    // 4. gather mean of h1 into aggin2 (warp per node)
    k_gather_w<2><<<(N_NODES + 7) / 8, 256>>>(p_h1, p_aggin2);

    // 5+6. fused GEMM2 + pooling (h2 never materialized)
    {
        dim3 grid((N_NODES + GBM - 1) / GBM, HID / GBN);
        k_gemm_tc<1><<<grid, 256>>>(p_h1, p_whi + 65536, p_wlo + 65536, EMB,
                                    p_aggin2, p_whi + 196608, p_wlo + 196608, EMB,
                                    b2, nullptr, batch, N_NODES, HID);
    }

    // 7. heads
    k_head<<<N_GRAPHS, HID>>>(Wh, bh, Wc, bc, out_hidden, out_cell);

    // 8. logits
    k_logits<<<N_GRAPHS, VOCAB>>>(out_hidden, Wout, bout, out_logits);
}

// round 10
// speedup vs baseline: 1.0137x; 1.0137x over previous
#include <cuda_runtime.h>
#include <cuda_bf16.h>
#include <cstdint>

#define N_NODES 50000
#define N_EDGES 800000
#define N_GRAPHS 64
#define FEAT 128
#define EMB 256
#define HID 512
#define VOCAB 512
#define NBLK_SCAN ((N_NODES + 255) / 256)   // 196

// ---------------- scratch (device globals; no allocation allowed) ----------
__device__ float g_aggin1[(size_t)N_NODES * FEAT];
__device__ float g_aggin2[(size_t)N_NODES * EMB];
__device__ float g_h1[(size_t)N_NODES * EMB];
__device__ int   g_deg[N_NODES];
__device__ int   g_rowstart[N_NODES];
__device__ int   g_cursor[N_NODES];
__device__ int   g_srcs[N_EDGES];
__device__ int   g_bsum[NBLK_SCAN];
__device__ int   g_boff[NBLK_SCAN];
__device__ float g_pooled[N_GRAPHS * HID];
__device__ float g_gcnt[N_GRAPHS];

// bf16 hi/lo weight copies: W_root1 @0 (32768), W_rel1 @32768,
// W_root2 @65536 (131072), W_rel2 @196608 (131072). total 327680.
#define W_TOTAL 327680
__device__ __nv_bfloat16 g_whi[W_TOTAL];
__device__ __nv_bfloat16 g_wlo[W_TOTAL];

// ---------------- small helpers ---------------------------------------------
__device__ __forceinline__ uint32_t smem_u32(const void* p) {
    return (uint32_t)__cvta_generic_to_shared(p);
}
__device__ __forceinline__ void ldsm_x4(uint32_t& r0, uint32_t& r1,
                                        uint32_t& r2, uint32_t& r3, uint32_t a) {
    asm volatile("ldmatrix.sync.aligned.m8n8.x4.shared.b16 {%0,%1,%2,%3},[%4];"
                 : "=r"(r0), "=r"(r1), "=r"(r2), "=r"(r3) : "r"(a));
}
__device__ __forceinline__ void ldsm_x4t(uint32_t& r0, uint32_t& r1,
                                         uint32_t& r2, uint32_t& r3, uint32_t a) {
    asm volatile("ldmatrix.sync.aligned.m8n8.x4.trans.shared.b16 {%0,%1,%2,%3},[%4];"
                 : "=r"(r0), "=r"(r1), "=r"(r2), "=r"(r3) : "r"(a));
}
__device__ __forceinline__ void mma_bf16(float* c, const uint32_t* a, const uint32_t* b) {
    asm volatile(
        "mma.sync.aligned.m16n8k16.row.col.f32.bf16.bf16.f32 "
        "{%0,%1,%2,%3},{%4,%5,%6,%7},{%8,%9},{%0,%1,%2,%3};"
        : "+f"(c[0]), "+f"(c[1]), "+f"(c[2]), "+f"(c[3])
        : "r"(a[0]), "r"(a[1]), "r"(a[2]), "r"(a[3]), "r"(b[0]), "r"(b[1]));
}
__device__ __forceinline__ uint32_t pack_bf2(__nv_bfloat16 x, __nv_bfloat16 y) {
    __nv_bfloat162 v = __halves2bfloat162(x, y);
    return *reinterpret_cast<uint32_t*>(&v);
}

// ---------------- weight split + zero scratch (merged) ----------------------
__global__ void k_wconv_zero(const float* __restrict__ w0, const float* __restrict__ w1,
                             const float* __restrict__ w2, const float* __restrict__ w3) {
    int i0 = blockIdx.x * blockDim.x + threadIdx.x;
    int stride = gridDim.x * blockDim.x;
    for (int i = i0; i < W_TOTAL; i += stride) {
        const float* src; int off;
        if (i < 32768)       { src = w0; off = i; }
        else if (i < 65536)  { src = w1; off = i - 32768; }
        else if (i < 196608) { src = w2; off = i - 65536; }
        else                 { src = w3; off = i - 196608; }
        float v = src[off];
        __nv_bfloat16 h = __float2bfloat16(v);
        g_whi[i] = h;
        g_wlo[i] = __float2bfloat16(v - __bfloat162float(h));
    }
    for (int j = i0; j < N_NODES; j += stride) g_deg[j] = 0;
    for (int j = i0; j < N_GRAPHS * HID; j += stride) g_pooled[j] = 0.f;
    for (int j = i0; j < N_GRAPHS; j += stride) g_gcnt[j] = 0.f;
}

// ---------------- in-degree histogram + per-graph counts (merged) -----------
__global__ void k_hist(const int* __restrict__ ei, const int* __restrict__ batch) {
    int i = blockIdx.x * blockDim.x + threadIdx.x;
    int stride = gridDim.x * blockDim.x;
    for (int e = i; e < N_EDGES; e += stride)
        atomicAdd(&g_deg[ei[N_EDGES + e]], 1);
    for (int v = i; v < N_NODES; v += stride)
        atomicAdd(&g_gcnt[batch[v]], 1.f);
}

// ---------------- 3-phase multi-block exclusive scan of g_deg ----------------
__global__ __launch_bounds__(256)
void k_scan1() {                       // per-block sums
    __shared__ int red[8];
    int b = blockIdx.x, t = threadIdx.x;
    int idx = b * 256 + t;
    int v = (idx < N_NODES) ? g_deg[idx] : 0;
    #pragma unroll
    for (int o = 16; o > 0; o >>= 1) v += __shfl_down_sync(0xffffffffu, v, o);
    if ((t & 31) == 0) red[t >> 5] = v;
    __syncthreads();
    if (t < 8) {
        int s = red[t];
        #pragma unroll
        for (int o = 4; o > 0; o >>= 1) s += __shfl_down_sync(0xffu, s, o);
        if (t == 0) g_bsum[b] = s;
    }
}

__global__ __launch_bounds__(256)
void k_scan2() {                       // scan of 196 block sums (1 block)
    __shared__ int s[256];
    int t = threadIdx.x;
    int v = (t < NBLK_SCAN) ? g_bsum[t] : 0;
    s[t] = v;
    __syncthreads();
    for (int off = 1; off < 256; off <<= 1) {
        int u = (t >= off) ? s[t - off] : 0;
        __syncthreads();
        s[t] += u;
        __syncthreads();
    }
    if (t < NBLK_SCAN) g_boff[t] = (t == 0) ? 0 : s[t - 1];
}

__global__ __launch_bounds__(256)
void k_scan3() {                       // local scan + block offset
    __shared__ int s[256];
    int b = blockIdx.x, t = threadIdx.x;
    int idx = b * 256 + t;
    int v = (idx < N_NODES) ? g_deg[idx] : 0;
    s[t] = v;
    __syncthreads();
    for (int off = 1; off < 256; off <<= 1) {
        int u = (t >= off) ? s[t - off] : 0;
        __syncthreads();
        s[t] += u;
        __syncthreads();
    }
    if (idx < N_NODES) {
        int excl = ((t == 0) ? 0 : s[t - 1]) + g_boff[b];
        g_rowstart[idx] = excl;
        g_cursor[idx] = excl;
    }
}

// ---------------- fill sorted src list by dst bin ----------------------------
__global__ void k_fill(const int* __restrict__ ei) {
    int i = blockIdx.x * blockDim.x + threadIdx.x;
    int stride = gridDim.x * blockDim.x;
    for (int e = i; e < N_EDGES; e += stride) {
        int src = ei[e];
        int dst = ei[N_EDGES + e];
        int pos = atomicAdd(&g_cursor[dst], 1);
        g_srcs[pos] = src;
    }
}

// ---------------- gather: warp per node, agg[v] = mean of feat[src] ---------
// F4 = number of float4 per lane (F/128). cols handled: lane*4 + c*128
template<int F4>
__global__ __launch_bounds__(256)
void k_gather_w(const float* __restrict__ feat, float* __restrict__ agg) {
    const int F = F4 * 128;
    int w = (blockIdx.x * blockDim.x + threadIdx.x) >> 5;
    if (w >= N_NODES) return;
    int lane = threadIdx.x & 31;
    int start = g_rowstart[w];
    int d = g_deg[w];

    float4 acc[4][F4];
    #pragma unroll
    for (int u = 0; u < 4; u++)
        #pragma unroll
        for (int c = 0; c < F4; c++)
            acc[u][c] = make_float4(0.f, 0.f, 0.f, 0.f);

    int i = 0;
    for (; i + 4 <= d; i += 4) {
        #pragma unroll
        for (int u = 0; u < 4; u++) {
            int src = g_srcs[start + i + u];
            const float* row = feat + (long long)src * F + lane * 4;
            #pragma unroll
            for (int c = 0; c < F4; c++) {
                float4 v = *reinterpret_cast<const float4*>(row + c * 128);
                acc[u][c].x += v.x; acc[u][c].y += v.y;
                acc[u][c].z += v.z; acc[u][c].w += v.w;
            }
        }
    }
    for (; i < d; i++) {
        int src = g_srcs[start + i];
        const float* row = feat + (long long)src * F + lane * 4;
        #pragma unroll
        for (int c = 0; c < F4; c++) {
            float4 v = *reinterpret_cast<const float4*>(row + c * 128);
            acc[0][c].x += v.x; acc[0][c].y += v.y;
            acc[0][c].z += v.z; acc[0][c].w += v.w;
        }
    }
    float inv = 1.f / fmaxf((float)d, 1.f);
    float* dstrow = agg + (long long)w * F + lane * 4;
    #pragma unroll
    for (int c = 0; c < F4; c++) {
        float4 r;
        r.x = (acc[0][c].x + acc[1][c].x + acc[2][c].x + acc[3][c].x) * inv;
        r.y = (acc[0][c].y + acc[1][c].y + acc[2][c].y + acc[3][c].y) * inv;
        r.z = (acc[0][c].z + acc[1][c].z + acc[2][c].z + acc[3][c].z) * inv;
        r.w = (acc[0][c].w + acc[1][c].w + acc[2][c].w + acc[3][c].w) * inv;
        *reinterpret_cast<float4*>(dstrow + c * 128) = r;
    }
}

// ---------------- tensor-core dual GEMM (bf16x3 fp32 emulation) -------------
// C[M,N] = relu(A1@B1 + A2@B2 + bias)
// POOL=0: store C.  POOL=1: segment-reduce by batch[] into g_pooled.
#define GBM 128
#define GBN 128
#define GBK 32
#define SA 40
#define SB 136

template<int POOL>
__global__ __launch_bounds__(256, 2)
void k_gemm_tc(const float* __restrict__ A1,
               const __nv_bfloat16* __restrict__ B1h, const __nv_bfloat16* __restrict__ B1l,
               int K1,
               const float* __restrict__ A2,
               const __nv_bfloat16* __restrict__ B2h, const __nv_bfloat16* __restrict__ B2l,
               int K2,
               const float* __restrict__ bias,
               float* __restrict__ C,
               const int* __restrict__ batch,
               int M, int N) {
    __shared__ __align__(16) __nv_bfloat16 Ash[GBM * SA];
    __shared__ __align__(16) __nv_bfloat16 Asl[GBM * SA];
    __shared__ __align__(16) __nv_bfloat16 Bsh[GBK * SB];
    __shared__ __align__(16) __nv_bfloat16 Bsl[GBK * SB];

    int tid = threadIdx.x, lane = tid & 31, warp = tid >> 5;
    int wm = warp & 3, wn = warp >> 2;
    int bm = blockIdx.x * GBM, bn = blockIdx.y * GBN;

    float acc[2][8][4];
    #pragma unroll
    for (int mi = 0; mi < 2; mi++)
        #pragma unroll
        for (int ni = 0; ni < 8; ni++)
            #pragma unroll
            for (int r = 0; r < 4; r++) acc[mi][ni][r] = 0.f;

    int a_row16 = lane & 15;
    int a_koff = (lane >> 4) << 3;
    int b_krow = lane & 15;
    int b_noff = (lane >> 4) << 3;

    for (int pass = 0; pass < 2; pass++) {
        const float* A = pass ? A2 : A1;
        const __nv_bfloat16* Bhg = pass ? B2h : B1h;
        const __nv_bfloat16* Blg = pass ? B2l : B1l;
        int K = pass ? K2 : K1;

        for (int k0 = 0; k0 < K; k0 += GBK) {
            #pragma unroll
            for (int i = 0; i < 4; i++) {
                int f4 = tid + i * 256;
                int row = f4 >> 3;
                int c4 = (f4 & 7) * 4;
                float4 v = make_float4(0.f, 0.f, 0.f, 0.f);
                int gr = bm + row;
                if (gr < M)
                    v = *reinterpret_cast<const float4*>(A + (long long)gr * K + k0 + c4);
                __nv_bfloat16 hx = __float2bfloat16(v.x);
                __nv_bfloat16 hy = __float2bfloat16(v.y);
                __nv_bfloat16 hz = __float2bfloat16(v.z);
                __nv_bfloat16 hw = __float2bfloat16(v.w);
                uint2 hp = make_uint2(pack_bf2(hx, hy), pack_bf2(hz, hw));
                *reinterpret_cast<uint2*>(&Ash[row * SA + c4]) = hp;
                __nv_bfloat16 lx = __float2bfloat16(v.x - __bfloat162float(hx));
                __nv_bfloat16 ly = __float2bfloat16(v.y - __bfloat162float(hy));
                __nv_bfloat16 lz = __float2bfloat16(v.z - __bfloat162float(hz));
                __nv_bfloat16 lw = __float2bfloat16(v.w - __bfloat162float(hw));
                uint2 lp = make_uint2(pack_bf2(lx, ly), pack_bf2(lz, lw));
                *reinterpret_cast<uint2*>(&Asl[row * SA + c4]) = lp;
            }
            #pragma unroll
            for (int i = 0; i < 4; i++) {
                int f = tid + i * 256;
                const __nv_bfloat16* src = (f < 512) ? Bhg : Blg;
                __nv_bfloat16* dst = (f < 512) ? Bsh : Bsl;
                int rem = f & 511;
                int r = rem >> 4;
                int c8 = (rem & 15) * 8;
                uint4 v = *reinterpret_cast<const uint4*>(
                    src + (long long)(k0 + r) * N + bn + c8);
                *reinterpret_cast<uint4*>(dst + r * SB + c8) = v;
            }
            __syncthreads();

            #pragma unroll
            for (int kk = 0; kk < GBK; kk += 16) {
                uint32_t afh[2][4], afl[2][4];
                #pragma unroll
                for (int mi = 0; mi < 2; mi++) {
                    int row = wm * 32 + mi * 16 + a_row16;
                    ldsm_x4(afh[mi][0], afh[mi][1], afh[mi][2], afh[mi][3],
                            smem_u32(&Ash[row * SA + kk + a_koff]));
                    ldsm_x4(afl[mi][0], afl[mi][1], afl[mi][2], afl[mi][3],
                            smem_u32(&Asl[row * SA + kk + a_koff]));
                }
                #pragma unroll
                for (int nj = 0; nj < 4; nj++) {
                    int ncol = wn * 64 + nj * 16 + b_noff;
                    int krow = kk + b_krow;
                    uint32_t bh[4], bl[4];
                    ldsm_x4t(bh[0], bh[1], bh[2], bh[3],
                             smem_u32(&Bsh[krow * SB + ncol]));
                    ldsm_x4t(bl[0], bl[1], bl[2], bl[3],
                             smem_u32(&Bsl[krow * SB + ncol]));
                    #pragma unroll
                    for (int mi = 0; mi < 2; mi++) {
                        mma_bf16(acc[mi][nj * 2],     afh[mi], bh);
                        mma_bf16(acc[mi][nj * 2],     afh[mi], bl);
                        mma_bf16(acc[mi][nj * 2],     afl[mi], bh);
                        mma_bf16(acc[mi][nj * 2 + 1], afh[mi], bh + 2);
                        mma_bf16(acc[mi][nj * 2 + 1], afh[mi], bl + 2);
                        mma_bf16(acc[mi][nj * 2 + 1], afl[mi], bh + 2);
                    }
                }
            }
            __syncthreads();
        }
    }

    int g = lane >> 2, tg = lane & 3;
    int m0 = bm + wm * 32;
    int coln = bn + wn * 64;

    float bb[16];
    #pragma unroll
    for (int ni = 0; ni < 8; ni++) {
        bb[ni * 2]     = bias[coln + ni * 8 + tg * 2];
        bb[ni * 2 + 1] = bias[coln + ni * 8 + tg * 2 + 1];
    }

    if (POOL == 0) {
        #pragma unroll
        for (int mi = 0; mi < 2; mi++) {
            int row_lo = m0 + mi * 16 + g;
            int row_hi = row_lo + 8;
            #pragma unroll
            for (int ni = 0; ni < 8; ni++) {
                int col = coln + ni * 8 + tg * 2;
                if (row_lo < M) {
                    float2 v;
                    v.x = fmaxf(acc[mi][ni][0] + bb[ni * 2], 0.f);
                    v.y = fmaxf(acc[mi][ni][1] + bb[ni * 2 + 1], 0.f);
                    *reinterpret_cast<float2*>(C + (long long)row_lo * N + col) = v;
                }
                if (row_hi < M) {
                    float2 v;
                    v.x = fmaxf(acc[mi][ni][2] + bb[ni * 2], 0.f);
                    v.y = fmaxf(acc[mi][ni][3] + bb[ni * 2 + 1], 0.f);
                    *reinterpret_cast<float2*>(C + (long long)row_hi * N + col) = v;
                }
            }
        }
    } else {
        float sum[16];
        int prev = -1;
        #pragma unroll
        for (int slot = 0; slot < 4; slot++) {
            int mi = slot >> 1, half = slot & 1;
            int row = m0 + mi * 16 + half * 8 + g;
            if (row >= M) break;
            float v[16];
            #pragma unroll
            for (int ni = 0; ni < 8; ni++) {
                v[ni * 2]     = fmaxf(acc[mi][ni][half * 2]     + bb[ni * 2], 0.f);
                v[ni * 2 + 1] = fmaxf(acc[mi][ni][half * 2 + 1] + bb[ni * 2 + 1], 0.f);
            }
            int gid = batch[row];
            if (gid != prev) {
                if (prev >= 0) {
                    #pragma unroll
                    for (int j = 0; j < 16; j++)
                        atomicAdd(&g_pooled[prev * HID + coln + (j >> 1) * 8 + tg * 2 + (j & 1)],
                                  sum[j]);
                }
                prev = gid;
                #pragma unroll
                for (int j = 0; j < 16; j++) sum[j] = v[j];
            } else {
                #pragma unroll
                for (int j = 0; j < 16; j++) sum[j] += v[j];
            }
        }
        if (prev >= 0) {
            #pragma unroll
            for (int j = 0; j < 16; j++)
                atomicAdd(&g_pooled[prev * HID + coln + (j >> 1) * 8 + tg * 2 + (j & 1)],
                          sum[j]);
        }
    }
}

// ---------------- heads -----------------------------------------------------
__global__ __launch_bounds__(512)
void k_head(const float* __restrict__ Wh, const float* __restrict__ bh,
            const float* __restrict__ Wc, const float* __restrict__ bc,
            float* __restrict__ out_hidden, float* __restrict__ out_cell) {
    int g = blockIdx.x;
    int t = threadIdx.x;
    __shared__ float p[HID];
    float inv = 1.f / fmaxf(g_gcnt[g], 1.f);
    p[t] = g_pooled[g * HID + t] * inv;
    __syncthreads();
    float h = 0.f, c = 0.f;
    #pragma unroll 8
    for (int k = 0; k < HID; k++) {
        float pk = p[k];
        h = fmaf(pk, Wh[k * HID + t], h);
        c = fmaf(pk, Wc[k * HID + t], c);
    }
    out_hidden[g * HID + t] = h + bh[t];
    out_cell[g * HID + t]   = c + bc[t];
}

// ---------------- logits = log_softmax(hidden @ Wout + bout) ----------------
__global__ __launch_bounds__(512)
void k_logits(const float* __restrict__ hidden,
              const float* __restrict__ Wout, const float* __restrict__ bout,
              float* __restrict__ logits) {
    int g = blockIdx.x;
    int t = threadIdx.x;
    __shared__ float h[HID];
    __shared__ float red[VOCAB];
    h[t] = hidden[g * HID + t];
    __syncthreads();
    float z = bout[t];
    #pragma unroll 8
    for (int k = 0; k < HID; k++)
        z = fmaf(h[k], Wout[k * VOCAB + t], z);

    red[t] = z;
    __syncthreads();
    for (int s = 256; s > 0; s >>= 1) {
        if (t < s) red[t] = fmaxf(red[t], red[t + s]);
        __syncthreads();
    }
    float mx = red[0];
    __syncthreads();
    red[t] = expf(z - mx);
    __syncthreads();
    for (int s = 256; s > 0; s >>= 1) {
        if (t < s) red[t] += red[t + s];
        __syncthreads();
    }
    float lse = logf(red[0]) + mx;
    logits[g * VOCAB + t] = z - lse;
}

// ---------------- launch ----------------------------------------------------
extern "C" void kernel_launch(void* const* d_in, const int* in_sizes, int n_in,
                              void* d_out, int out_size) {
    const float* x       = (const float*)d_in[1];
    const int*   ei      = (const int*)d_in[2];
    const int*   batch   = (const int*)d_in[3];
    const float* W_root1 = (const float*)d_in[4];
    const float* W_rel1  = (const float*)d_in[5];
    const float* b1      = (const float*)d_in[6];
    const float* W_root2 = (const float*)d_in[7];
    const float* W_rel2  = (const float*)d_in[8];
    const float* b2      = (const float*)d_in[9];
    const float* Wh      = (const float*)d_in[10];
    const float* bh      = (const float*)d_in[11];
    const float* Wc      = (const float*)d_in[12];
    const float* bc      = (const float*)d_in[13];
    const float* Wout    = (const float*)d_in[14];
    const float* bout    = (const float*)d_in[15];
    float* out = (float*)d_out;

    float *p_aggin1, *p_aggin2, *p_h1;
    __nv_bfloat16 *p_whi, *p_wlo;
    cudaGetSymbolAddress((void**)&p_aggin1, g_aggin1);
    cudaGetSymbolAddress((void**)&p_aggin2, g_aggin2);
    cudaGetSymbolAddress((void**)&p_h1, g_h1);
    cudaGetSymbolAddress((void**)&p_whi, g_whi);
    cudaGetSymbolAddress((void**)&p_wlo, g_wlo);

    float* out_logits = out;
    float* out_hidden = out + N_GRAPHS * HID;
    float* out_cell   = out + 2 * N_GRAPHS * HID;

    // 1. weight split + zero scratch, then CSR build (multi-block scan)
    k_wconv_zero<<<320, 256>>>(W_root1, W_rel1, W_root2, W_rel2);
    k_hist<<<1024, 256>>>(ei, batch);
    k_scan1<<<NBLK_SCAN, 256>>>();
    k_scan2<<<1, 256>>>();
    k_scan3<<<NBLK_SCAN, 256>>>();
    k_fill<<<1024, 256>>>(ei);

    // 2. gather mean of raw x into aggin1 (warp per node)
    k_gather_w<1><<<(N_NODES + 7) / 8, 256>>>(x, p_aggin1);

    // 3. h1 = relu(x@W_root1 + aggin1@W_rel1 + b1)   [tensor core]
    {
        dim3 grid((N_NODES + GBM - 1) / GBM, EMB / GBN);
        k_gemm_tc<0><<<grid, 256>>>(x, p_whi, p_wlo, FEAT,
                                    p_aggin1, p_whi + 32768, p_wlo + 32768, FEAT,
                                    b1, p_h1, nullptr, N_NODES, EMB);
    }

    // 4. gather mean of h1 into aggin2 (warp per node)
    k_gather_w<2><<<(N_NODES + 7) / 8, 256>>>(p_h1, p_aggin2);

    // 5+6. fused GEMM2 + pooling (h2 never materialized)
    {
        dim3 grid((N_NODES + GBM - 1) / GBM, HID / GBN);
        k_gemm_tc<1><<<grid, 256>>>(p_h1, p_whi + 65536, p_wlo + 65536, EMB,
                                    p_aggin2, p_whi + 196608, p_wlo + 196608, EMB,
                                    b2, nullptr, batch, N_NODES, HID);
    }

    // 7. heads
    k_head<<<N_GRAPHS, HID>>>(Wh, bh, Wc, bc, out_hidden, out_cell);

    // 8. logits
    k_logits<<<N_GRAPHS, VOCAB>>>(out_hidden, Wout, bout, out_logits);
}